// round 15
// baseline (speedup 1.0000x reference)
#include <cuda_runtime.h>
#include <cuda_fp16.h>
#include <cstdint>

typedef uint32_t u32;

// ---------------- device scratch (allocation-free rule) ----------------------
__device__ __align__(16) float g_planes[3 * 32 * 32 * 64]; // [plane][y][x][c]
__device__ __align__(16) u32   g_w1f[16 * 4 * 32 * 4];     // [nt][ks][lane][w] frag-packed
__device__ __align__(16) u32   g_w2f[16 * 8 * 32 * 4];     // [nt][ks][lane][w]

#define NPAIR 8
#define NT_P  10          // layer-1 n-tiles computed by the producer (ks2 0..4)
#define KS2_P 5

// smem u32 layout:
//   [0)      A1 rings: 8 pairs x 2 x 1024          = 16384
//   [16384)  a2 handoff: 8 pairs x 1536 (h@0,l@640)= 12288
//   [28672)  w1 frags                              =  8192
//   [36864)  w2 frags                              = 16384
//   [53248)  consts (b1*S2, b2, w3)                =   384
#define SM_A2X  16384
#define SM_W1   28672
#define SM_W2   36864
#define SM_CST  53248
#define SMEM_U32_TOTAL (53248 + 384)
#define SMEM_BYTES (SMEM_U32_TOTAL * 4)

// scaling keeps fp16 residuals out of the denormal range
#define S1      16384.0f
#define S2      4096.0f
#define INV_S2  (1.0f / 4096.0f)
#define SC      2048.0f
#define INV_SC  (1.0f / 2048.0f)
#define KS1S2   0.25f      // INV_S1 * S2 = 2^-14 * 2^12 (exact)

// ---------------- helpers ----------------------------------------------------
__device__ __forceinline__ float2 ldcg2(const float* p) {
    float2 v; asm("ld.global.cg.v2.f32 {%0,%1}, [%2];" : "=f"(v.x), "=f"(v.y) : "l"(p)); return v;
}
__device__ __forceinline__ u32 pk2(float x, float y) {   // lo=x, hi=y, one cvt
    u32 r; asm("cvt.rn.f16x2.f32 %0, %1, %2;" : "=r"(r) : "f"(y), "f"(x)); return r;
}
__device__ __forceinline__ void upk2(u32 v, float& lo, float& hi) {
    asm("{ .reg .b16 l, h; mov.b32 {l, h}, %2; cvt.f32.f16 %0, l; cvt.f32.f16 %1, h; }"
        : "=f"(lo), "=f"(hi) : "r"(v));
}
__device__ __forceinline__ float rf16(float x) {
    return __half2float(__float2half_rn(x));
}
__device__ __forceinline__ u32 pk2s(float x, float y) {  // scalar pack (prep)
    __half2 h = __halves2half2(__float2half_rn(x), __float2half_rn(y));
    return *(u32*)&h;
}
__device__ __forceinline__ void mma16(float* c, const u32* a, u32 b0, u32 b1) {
    asm volatile("mma.sync.aligned.m16n8k16.row.col.f32.f16.f16.f32 "
        "{%0,%1,%2,%3}, {%4,%5,%6,%7}, {%8,%9}, {%0,%1,%2,%3};"
        : "+f"(c[0]), "+f"(c[1]), "+f"(c[2]), "+f"(c[3])
        : "r"(a[0]), "r"(a[1]), "r"(a[2]), "r"(a[3]), "r"(b0), "r"(b1));
}
__device__ __forceinline__ void bar_sync64(int id) {
    asm volatile("bar.sync %0, 64;" :: "r"(id) : "memory");
}
__device__ __forceinline__ void bar_arrive64(int id) {
    asm volatile("bar.arrive %0, 64;" :: "r"(id) : "memory");
}

// ---------------- prep: planes channel-last; weights frag-packed hi + lo*2048
__global__ void prep_kernel(const float* __restrict__ pxy, const float* __restrict__ pyz,
                            const float* __restrict__ pxz, const float* __restrict__ w1,
                            const float* __restrict__ w2) {
    int idx = blockIdx.x * 256 + threadIdx.x;
    if (idx < 196608) {
        int pl = idx >> 16;
        int r  = idx & 65535;
        const float* src = (pl == 0) ? pxy : ((pl == 1) ? pyz : pxz);
        float v = src[r];
        int c = r >> 10, y = (r >> 5) & 31, x = r & 31;
        g_planes[(pl << 16) + (((y << 5) + x) << 6) + c] = v;
    } else if (idx < 196608 + 8192) {
        int i = idx - 196608;                       // w1: [n=128][k=64]
        int w = i & 3, lane = (i >> 2) & 31, ks = (i >> 7) & 3, nt = i >> 9;
        int g = lane >> 2, t = lane & 3;
        int n = nt * 8 + g;
        int k0 = ks * 16 + ((w & 1) << 3) + t * 2;
        float v0 = w1[n * 64 + k0], v1 = w1[n * 64 + k0 + 1];
        u32 val = (w < 2) ? pk2s(v0, v1)
                          : pk2s((v0 - rf16(v0)) * SC, (v1 - rf16(v1)) * SC);
        g_w1f[i] = val;
    } else if (idx < 196608 + 8192 + 16384) {
        int i = idx - (196608 + 8192);              // w2: [n=128][k=128]
        int w = i & 3, lane = (i >> 2) & 31, ks = (i >> 7) & 7, nt = i >> 10;
        int g = lane >> 2, t = lane & 3;
        int n = nt * 8 + g;
        int k0 = ks * 16 + ((w & 1) << 3) + t * 2;
        float v0 = w2[n * 128 + k0], v1 = w2[n * 128 + k0 + 1];
        u32 val = (w < 2) ? pk2s(v0, v1)
                          : pk2s((v0 - rf16(v0)) * SC, (v1 - rf16(v1)) * SC);
        g_w2f[i] = val;
    }
}

// ---------------- axis-hoisted bilinear sampling ------------------------------
struct Ax { int i; float w0, w1; int v0, v1; };
__device__ __forceinline__ Ax mkax(float g) {
    Ax a;
    float x = (g + 1.0f) * 15.5f;     // matches reference rounding
    float f = floorf(x);
    a.i = (int)f;
    a.w1 = x - f; a.w0 = 1.0f - a.w1;
    a.v0 = ((unsigned)a.i < 32u);
    a.v1 = ((unsigned)(a.i + 1) < 32u);
    return a;
}
__device__ __forceinline__ float2 sampA(const float* __restrict__ base, const Ax X, const Ax Y) {
    float2 acc = make_float2(0.f, 0.f);
    const float* p = base + (((Y.i << 5) + X.i) << 6);
    if (X.v0 & Y.v0) { float w = X.w0 * Y.w0; float2 v = ldcg2(p);
        acc.x = fmaf(w, v.x, acc.x); acc.y = fmaf(w, v.y, acc.y); }
    if (X.v1 & Y.v0) { float w = X.w1 * Y.w0; float2 v = ldcg2(p + 64);
        acc.x = fmaf(w, v.x, acc.x); acc.y = fmaf(w, v.y, acc.y); }
    if (X.v0 & Y.v1) { float w = X.w0 * Y.w1; float2 v = ldcg2(p + 2048);
        acc.x = fmaf(w, v.x, acc.x); acc.y = fmaf(w, v.y, acc.y); }
    if (X.v1 & Y.v1) { float w = X.w1 * Y.w1; float2 v = ldcg2(p + 2112);
        acc.x = fmaf(w, v.x, acc.x); acc.y = fmaf(w, v.y, acc.y); }
    return acc;
}

// sample one point r of slice at pbase into staging buffer awn
__device__ __forceinline__ void sample_point(
    const float* __restrict__ coords, int pbase, int r,
    const float* __restrict__ bs, u32* awn,
    int ks_s, int whi2, int tl, int sswz)
{
    const float* cp = coords + 3 * (pbase + r);
    float c0 = __ldg(cp), c1 = __ldg(cp + 1), c2 = __ldg(cp + 2);
    Ax A0 = mkax(c0), A1 = mkax(c1), A2 = mkax(c2);
    float2 fxy = sampA(bs,          A0, A1);
    float2 fyz = sampA(bs + 65536,  A1, A2);
    float2 fxz = sampA(bs + 131072, A0, A2);
    float f0 = fxy.x * fyz.x * fxz.x * S1;
    float f1 = fxy.y * fyz.y * fxz.y * S1;
    u32 hi = pk2(f0, f1);
    float r0, r1; upk2(hi, r0, r1);
    u32 lo = pk2((f0 - r0) * SC, (f1 - r1) * SC);
    int w_hi = (r >> 3) + whi2;
    int lcx  = (r & 7) * 4 + tl;
    int addr = (ks_s * 8 + w_hi) * 32 + (lcx ^ sswz);
    awn[addr]       = hi;
    awn[addr + 128] = lo;
}

// load swizzle-matched A1 fragments (both roles use this)
__device__ __forceinline__ void load_frags(const u32* awc, int lane, u32 ah[4][4], u32 al[4][4]) {
    #pragma unroll
    for (int ks = 0; ks < 4; ks++)
        #pragma unroll
        for (int w = 0; w < 4; w++) {
            int bank = lane ^ (ks * 4) ^ ((w & 2) * 8);
            ah[ks][w] = awc[(ks * 8 + w) * 32 + bank];
            al[ks][w] = awc[(ks * 8 + w + 4) * 32 + bank];
        }
}

// layer-1 body for one nt: returns packed a2 h/l words
__device__ __forceinline__ void l1_nt(
    int nt, int t, int lane, const uint4* w1f, const float* sB1s,
    const u32 ah[4][4], const u32 al[4][4],
    u32& hA, u32& hB, u32& lA, u32& lB)
{
    float c0[4] = {0.f, 0.f, 0.f, 0.f};
    float c1[4] = {0.f, 0.f, 0.f, 0.f};
    float c2[4] = {0.f, 0.f, 0.f, 0.f};
    #pragma unroll
    for (int ks = 0; ks < 4; ks++) {
        uint4 B = w1f[(nt * 4 + ks) * 32 + lane];
        mma16(c0, ah[ks], B.x, B.y);   // Ah*Bh
        mma16(c1, al[ks], B.x, B.y);   // (Al*SC)*Bh
        mma16(c2, ah[ks], B.z, B.w);   // Ah*(Bl*SC)
    }
    int n = nt * 8 + t * 2;
    float s0f = fmaf(c1[0] + c2[0], INV_SC, c0[0]);
    float s1f = fmaf(c1[1] + c2[1], INV_SC, c0[1]);
    float s2f = fmaf(c1[2] + c2[2], INV_SC, c0[2]);
    float s3f = fmaf(c1[3] + c2[3], INV_SC, c0[3]);
    float h0 = fmaxf(fmaf(s0f, KS1S2, sB1s[n]),     0.f);  // b1*S2 pre-folded
    float h1 = fmaxf(fmaf(s1f, KS1S2, sB1s[n + 1]), 0.f);
    float h2 = fmaxf(fmaf(s2f, KS1S2, sB1s[n]),     0.f);
    float h3 = fmaxf(fmaf(s3f, KS1S2, sB1s[n + 1]), 0.f);
    hA = pk2(h0, h1); hB = pk2(h2, h3);
    float r0, r1, r2, r3;
    upk2(hA, r0, r1); upk2(hB, r2, r3);
    lA = pk2((h0 - r0) * SC, (h1 - r1) * SC);
    lB = pk2((h2 - r2) * SC, (h3 - r3) * SC);
}

// ---------------- persistent warp-specialized fused kernel -------------------
__global__ __launch_bounds__(512, 1) void fused_kernel(
    const float* __restrict__ coords,
    const float* __restrict__ b1, const float* __restrict__ b2,
    const float* __restrict__ w3, const float* __restrict__ b3,
    float* __restrict__ out, int nslices)
{
    extern __shared__ __align__(16) u32 dsm[];
    float* sB1s = (float*)(dsm + SM_CST);     // b1 * S2
    float* sB2  = sB1s + 128;
    float* sW3  = sB2 + 128;

    int tid = threadIdx.x, lane = tid & 31, wid = tid >> 5;

    // ---- stage weights into smem (one-time, coalesced uint4 copies) ---------
    {
        uint4* dst = (uint4*)(dsm + SM_W1);
        const uint4* src = (const uint4*)g_w1f;
        #pragma unroll 4
        for (int i = tid; i < 2048; i += 512) dst[i] = src[i];
        uint4* dst2 = (uint4*)(dsm + SM_W2);
        const uint4* src2 = (const uint4*)g_w2f;
        #pragma unroll 8
        for (int i = tid; i < 4096; i += 512) dst2[i] = src2[i];
    }
    if (tid < 128) { sB1s[tid] = b1[tid] * S2; sB2[tid] = b2[tid]; sW3[tid] = w3[tid]; }
    __syncthreads();

    int pairid = wid & 7;
    bool producer = (wid < 8);
    int barPub = pairid * 2;                  // both roles bar.sync
    int barA2  = pairid * 2 + 1;              // P arrives, C syncs

    u32* buf0 = dsm + pairid * 2048;          // A1 ring (2 x 1024 u32)
    u32* buf1 = buf0 + 1024;
    u32* a2x  = dsm + SM_A2X + pairid * 1536; // h at [idx], l at [idx+640]

    const uint4* w1f = (const uint4*)(dsm + SM_W1);
    const uint4* w2f = (const uint4*)(dsm + SM_W2);

    int stride = gridDim.x * NPAIR;
    int s0 = blockIdx.x * NPAIR + pairid;
    int t = lane & 3, g = lane >> 2;

    if (producer) {
        // -------- sampler + layer-1(nt 0..NT_P-1) warp ------------------------
        const float* bs = g_planes + 2 * lane;
        int ks_s = lane >> 3;
        int whi2 = ((lane >> 2) & 1) * 2;
        int tl   = lane & 3;
        int sswz = ks_s * 4 + whi2 * 8;

        int p = 0;
        for (int s = s0; s < nslices; s += stride) {
            u32* b = p ? buf1 : buf0;
            #pragma unroll 4
            for (int r = 0; r < 16; r++)
                sample_point(coords, s * 16, r, bs, b, ks_s, whi2, tl, sswz);
            bar_sync64(barPub);               // publish A1 buffer

            u32 ah[4][4], al[4][4];
            load_frags(b, lane, ah, al);

            #pragma unroll 2
            for (int nt = 0; nt < NT_P; nt++) {
                u32 hA, hB, lA, lB;
                l1_nt(nt, t, lane, w1f, sB1s, ah, al, hA, hB, lA, lB);
                int ks2 = nt >> 1, w0 = (nt & 1) * 2;
                int idx = (ks2 * 4 + w0) * 32 + lane;
                a2x[idx]       = hA;  a2x[idx + 32]       = hB;
                a2x[idx + 640] = lA;  a2x[idx + 640 + 32] = lB;
            }
            bar_arrive64(barA2);              // a2 half published
            p ^= 1;
        }
    } else {
        // -------- layer-1(nt NT_P..15) + layer-2 + output warp ----------------
        float bb3 = __ldg(b3);

        int p = 0;
        for (int s = s0; s < nslices; s += stride) {
            bar_sync64(barPub);               // wait for A1 buffer
            u32* awc = p ? buf1 : buf0;
            int pbase = s * 16;

            u32 ah[4][4], al[4][4];
            load_frags(awc, lane, ah, al);

            u32 a2h[8][4], a2l[8][4];
            #pragma unroll 2
            for (int nt = NT_P; nt < 16; nt++) {
                u32 hA, hB, lA, lB;
                l1_nt(nt, t, lane, w1f, sB1s, ah, al, hA, hB, lA, lB);
                int ks2 = nt >> 1, w0 = (nt & 1) * 2;
                a2h[ks2][w0] = hA; a2h[ks2][w0 + 1] = hB;
                a2l[ks2][w0] = lA; a2l[ks2][w0 + 1] = lB;
            }

            bar_sync64(barA2);                // wait for producer's a2 half
            #pragma unroll
            for (int k = 0; k < KS2_P; k++)
                #pragma unroll
                for (int w = 0; w < 4; w++) {
                    int idx = (k * 4 + w) * 32 + lane;
                    a2h[k][w] = a2x[idx];
                    a2l[k][w] = a2x[idx + 640];
                }

            // ---- layer 2: 16 nt, 3 chains, all-register A, unroll 2 ---------
            float plo = 0.f, phi = 0.f;
            #pragma unroll 2
            for (int nt = 0; nt < 16; nt++) {
                float c0[4] = {0.f, 0.f, 0.f, 0.f};
                float c1[4] = {0.f, 0.f, 0.f, 0.f};
                float c2[4] = {0.f, 0.f, 0.f, 0.f};
                #pragma unroll
                for (int ks = 0; ks < 8; ks++) {
                    uint4 B = w2f[(nt * 8 + ks) * 32 + lane];
                    mma16(c0, a2h[ks], B.x, B.y);
                    mma16(c1, a2l[ks], B.x, B.y);
                    mma16(c2, a2h[ks], B.z, B.w);
                }
                int n = nt * 8 + t * 2;
                float w30 = sW3[n], w31 = sW3[n + 1];
                float bb0 = sB2[n], bb1 = sB2[n + 1];
                float v0 = fmaf(fmaf(c1[0] + c2[0], INV_SC, c0[0]), INV_S2, bb0);
                float v1 = fmaf(fmaf(c1[1] + c2[1], INV_SC, c0[1]), INV_S2, bb1);
                float v2 = fmaf(fmaf(c1[2] + c2[2], INV_SC, c0[2]), INV_S2, bb0);
                float v3 = fmaf(fmaf(c1[3] + c2[3], INV_SC, c0[3]), INV_S2, bb1);
                plo = fmaf(fmaxf(v0, 0.f), w30, plo);
                plo = fmaf(fmaxf(v1, 0.f), w31, plo);
                phi = fmaf(fmaxf(v2, 0.f), w30, phi);
                phi = fmaf(fmaxf(v3, 0.f), w31, phi);
            }
            plo += __shfl_xor_sync(0xffffffffu, plo, 1);
            plo += __shfl_xor_sync(0xffffffffu, plo, 2);
            phi += __shfl_xor_sync(0xffffffffu, phi, 1);
            phi += __shfl_xor_sync(0xffffffffu, phi, 2);
            if (t == 0) {
                out[pbase + g]     = plo + bb3;
                out[pbase + g + 8] = phi + bb3;
            }
            p ^= 1;
        }
    }
}

// ---------------- launch ------------------------------------------------------
extern "C" void kernel_launch(void* const* d_in, const int* in_sizes, int n_in,
                              void* d_out, int out_size) {
    const float* coords = (const float*)d_in[0];
    const float* pxy    = (const float*)d_in[1];
    const float* pyz    = (const float*)d_in[2];
    const float* pxz    = (const float*)d_in[3];
    const float* w1     = (const float*)d_in[4];
    const float* b1     = (const float*)d_in[5];
    const float* w2     = (const float*)d_in[6];
    const float* b2     = (const float*)d_in[7];
    const float* w3     = (const float*)d_in[8];
    const float* b3     = (const float*)d_in[9];
    float* out = (float*)d_out;

    int M = in_sizes[0] / 3;       // 1048576
    int nslices = M / 16;          // 65536

    prep_kernel<<<864, 256>>>(pxy, pyz, pxz, w1, w2);

    int dev = 0, nsm = 148;
    cudaGetDevice(&dev);
    cudaDeviceGetAttribute(&nsm, cudaDevAttrMultiProcessorCount, dev);

    cudaFuncSetAttribute(fused_kernel, cudaFuncAttributeMaxDynamicSharedMemorySize, SMEM_BYTES);
    fused_kernel<<<nsm, 512, SMEM_BYTES>>>(coords, b1, b2, w3, b3, out, nslices);
}

// round 16
// speedup vs baseline: 1.2257x; 1.2257x over previous
#include <cuda_runtime.h>
#include <cuda_fp16.h>
#include <cstdint>

typedef uint32_t u32;

// ---------------- device scratch (allocation-free rule) ----------------------
__device__ __align__(16) float g_planes[3 * 32 * 32 * 64]; // [plane][y][x][c]
__device__ __align__(16) u32   g_w1f[16 * 4 * 32 * 4];     // [nt][ks][lane][w] hi+lo frags
__device__ __align__(16) u32   g_w2h[16 * 8 * 32 * 2];     // [nt][ks][lane][2] hi-only frags

#define NPAIR 8
// smem u32 layout:
//   [0)       A1 rings: 8 pairs x 2 x 1024  = 16384
//   [16384)   w1 frags (hi+lo)              =  8192
//   [24576)   w2 frags (hi only)            =  8192
//   [32768)   consts (b1,b2,w3)             =   384
#define SM_W1   16384
#define SM_W2   24576
#define SM_CST  32768
#define SMEM_U32_TOTAL (32768 + 384)
#define SMEM_BYTES (SMEM_U32_TOTAL * 4)

// scaling keeps fp16 residuals out of the denormal range
#define S1      16384.0f
#define INV_S1  (1.0f / 16384.0f)
#define S2      4096.0f
#define INV_S2  (1.0f / 4096.0f)
#define SC      2048.0f
#define INV_SC  (1.0f / 2048.0f)

// ---------------- helpers ----------------------------------------------------
__device__ __forceinline__ float2 ldcg2(const float* p) {
    float2 v; asm("ld.global.cg.v2.f32 {%0,%1}, [%2];" : "=f"(v.x), "=f"(v.y) : "l"(p)); return v;
}
// pack (lo=x, hi=y) to f16x2 in ONE cvt
__device__ __forceinline__ u32 pk2(float x, float y) {
    u32 r; asm("cvt.rn.f16x2.f32 %0, %1, %2;" : "=r"(r) : "f"(y), "f"(x)); return r;
}
// unpack f16x2 to two floats (rounded values)
__device__ __forceinline__ void upk2(u32 v, float& lo, float& hi) {
    asm("{ .reg .b16 l, h; mov.b32 {l, h}, %2; cvt.f32.f16 %0, l; cvt.f32.f16 %1, h; }"
        : "=f"(lo), "=f"(hi) : "r"(v));
}
__device__ __forceinline__ float rf16(float x) {
    return __half2float(__float2half_rn(x));
}
__device__ __forceinline__ u32 pk2s(float x, float y) {  // scalar pack (prep)
    __half2 h = __halves2half2(__float2half_rn(x), __float2half_rn(y));
    return *(u32*)&h;
}
__device__ __forceinline__ void mma16(float* c, const u32* a, u32 b0, u32 b1) {
    asm volatile("mma.sync.aligned.m16n8k16.row.col.f32.f16.f16.f32 "
        "{%0,%1,%2,%3}, {%4,%5,%6,%7}, {%8,%9}, {%0,%1,%2,%3};"
        : "+f"(c[0]), "+f"(c[1]), "+f"(c[2]), "+f"(c[3])
        : "r"(a[0]), "r"(a[1]), "r"(a[2]), "r"(a[3]), "r"(b0), "r"(b1));
}
__device__ __forceinline__ void pair_bar(int id) {
    asm volatile("bar.sync %0, 64;" :: "r"(id) : "memory");
}

// ---------------- prep: planes channel-last; w1 hi+lo, w2 hi-only -------------
__global__ void prep_kernel(const float* __restrict__ pxy, const float* __restrict__ pyz,
                            const float* __restrict__ pxz, const float* __restrict__ w1,
                            const float* __restrict__ w2) {
    int idx = blockIdx.x * 256 + threadIdx.x;
    if (idx < 196608) {
        int pl = idx >> 16;
        int r  = idx & 65535;
        const float* src = (pl == 0) ? pxy : ((pl == 1) ? pyz : pxz);
        float v = src[r];
        int c = r >> 10, y = (r >> 5) & 31, x = r & 31;
        g_planes[(pl << 16) + (((y << 5) + x) << 6) + c] = v;
    } else if (idx < 196608 + 8192) {
        int i = idx - 196608;                       // w1: [n=128][k=64], hi+lo
        int w = i & 3, lane = (i >> 2) & 31, ks = (i >> 7) & 3, nt = i >> 9;
        int g = lane >> 2, t = lane & 3;
        int n = nt * 8 + g;
        int k0 = ks * 16 + ((w & 1) << 3) + t * 2;
        float v0 = w1[n * 64 + k0], v1 = w1[n * 64 + k0 + 1];
        u32 val = (w < 2) ? pk2s(v0, v1)
                          : pk2s((v0 - rf16(v0)) * SC, (v1 - rf16(v1)) * SC);
        g_w1f[i] = val;
    } else if (idx < 196608 + 8192 + 8192) {
        int i = idx - (196608 + 8192);              // w2: [n=128][k=128], hi only
        int w = i & 1, lane = (i >> 1) & 31, ks = (i >> 6) & 7, nt = i >> 9;
        int g = lane >> 2, t = lane & 3;
        int n = nt * 8 + g;
        int k0 = ks * 16 + (w << 3) + t * 2;
        float v0 = w2[n * 128 + k0], v1 = w2[n * 128 + k0 + 1];
        g_w2h[i] = pk2s(v0, v1);
    }
}

// ---------------- axis-hoisted bilinear sampling ------------------------------
struct Ax { int i; float w0, w1; int v0, v1; };
__device__ __forceinline__ Ax mkax(float g) {
    Ax a;
    float x = (g + 1.0f) * 15.5f;     // matches reference rounding
    float f = floorf(x);
    a.i = (int)f;
    a.w1 = x - f; a.w0 = 1.0f - a.w1;
    a.v0 = ((unsigned)a.i < 32u);
    a.v1 = ((unsigned)(a.i + 1) < 32u);
    return a;
}
__device__ __forceinline__ float2 sampA(const float* __restrict__ base, const Ax X, const Ax Y) {
    float2 acc = make_float2(0.f, 0.f);
    const float* p = base + (((Y.i << 5) + X.i) << 6);
    if (X.v0 & Y.v0) { float w = X.w0 * Y.w0; float2 v = ldcg2(p);
        acc.x = fmaf(w, v.x, acc.x); acc.y = fmaf(w, v.y, acc.y); }
    if (X.v1 & Y.v0) { float w = X.w1 * Y.w0; float2 v = ldcg2(p + 64);
        acc.x = fmaf(w, v.x, acc.x); acc.y = fmaf(w, v.y, acc.y); }
    if (X.v0 & Y.v1) { float w = X.w0 * Y.w1; float2 v = ldcg2(p + 2048);
        acc.x = fmaf(w, v.x, acc.x); acc.y = fmaf(w, v.y, acc.y); }
    if (X.v1 & Y.v1) { float w = X.w1 * Y.w1; float2 v = ldcg2(p + 2112);
        acc.x = fmaf(w, v.x, acc.x); acc.y = fmaf(w, v.y, acc.y); }
    return acc;
}

// sample one point r of slice at pbase into staging buffer awn
__device__ __forceinline__ void sample_point(
    const float* __restrict__ coords, int pbase, int r,
    const float* __restrict__ bs, u32* awn,
    int ks_s, int whi2, int tl, int sswz)
{
    const float* cp = coords + 3 * (pbase + r);
    float c0 = __ldg(cp), c1 = __ldg(cp + 1), c2 = __ldg(cp + 2);
    Ax A0 = mkax(c0), A1 = mkax(c1), A2 = mkax(c2);
    float2 fxy = sampA(bs,          A0, A1);
    float2 fyz = sampA(bs + 65536,  A1, A2);
    float2 fxz = sampA(bs + 131072, A0, A2);
    float f0 = fxy.x * fyz.x * fxz.x * S1;
    float f1 = fxy.y * fyz.y * fxz.y * S1;
    u32 hi = pk2(f0, f1);
    float r0, r1; upk2(hi, r0, r1);
    u32 lo = pk2((f0 - r0) * SC, (f1 - r1) * SC);
    int w_hi = (r >> 3) + whi2;
    int lcx  = (r & 7) * 4 + tl;
    int addr = (ks_s * 8 + w_hi) * 32 + (lcx ^ sswz);
    awn[addr]       = hi;
    awn[addr + 128] = lo;
}

// ---------------- persistent warp-specialized fused kernel -------------------
__global__ __launch_bounds__(512, 1) void fused_kernel(
    const float* __restrict__ coords,
    const float* __restrict__ b1, const float* __restrict__ b2,
    const float* __restrict__ w3, const float* __restrict__ b3,
    float* __restrict__ out, int nslices)
{
    extern __shared__ __align__(16) u32 dsm[];
    float* sB1 = (float*)(dsm + SM_CST);
    float* sB2 = sB1 + 128;
    float* sW3 = sB2 + 128;

    int tid = threadIdx.x, lane = tid & 31, wid = tid >> 5;

    // ---- stage weights into smem (one-time, coalesced copies) ---------------
    {
        uint4* dst = (uint4*)(dsm + SM_W1);
        const uint4* src = (const uint4*)g_w1f;
        #pragma unroll 4
        for (int i = tid; i < 2048; i += 512) dst[i] = src[i];
        uint4* dst2 = (uint4*)(dsm + SM_W2);
        const uint4* src2 = (const uint4*)g_w2h;
        #pragma unroll 4
        for (int i = tid; i < 2048; i += 512) dst2[i] = src2[i];
    }
    if (tid < 128) { sB1[tid] = b1[tid]; sB2[tid] = b2[tid]; sW3[tid] = w3[tid]; }
    __syncthreads();

    int pairid = wid & 7;
    bool producer = (wid < 8);
    int barid = pairid + 1;                       // ids 1..8 (0 = __syncthreads)

    u32* buf0 = dsm + pairid * 2048;              // A1 ring (2 x 1024 u32)
    u32* buf1 = buf0 + 1024;

    int stride = gridDim.x * NPAIR;
    int s0 = blockIdx.x * NPAIR + pairid;

    if (producer) {
        // ------------------ sampler warp --------------------------------------
        const float* bs = g_planes + 2 * lane;
        int ks_s = lane >> 3;
        int whi2 = ((lane >> 2) & 1) * 2;
        int tl   = lane & 3;
        int sswz = ks_s * 4 + whi2 * 8;

        int p = 0;
        for (int s = s0; s < nslices; s += stride) {
            u32* b = p ? buf1 : buf0;
            #pragma unroll 4
            for (int r = 0; r < 16; r++)
                sample_point(coords, s * 16, r, bs, b, ks_s, whi2, tl, sswz);
            pair_bar(barid);                      // publish buffer, swap
            p ^= 1;
        }
    } else {
        // ------------------ MMA warp ------------------------------------------
        int g = lane >> 2, t = lane & 3;
        float bb3 = __ldg(b3);
        const uint4* w1f = (const uint4*)(dsm + SM_W1);   // hi+lo frags
        const uint2* w2h = (const uint2*)(dsm + SM_W2);   // hi-only frags

        int p = 0;
        for (int s = s0; s < nslices; s += stride) {
            pair_bar(barid);                      // wait for buffer p
            u32* awc = p ? buf1 : buf0;
            int pbase = s * 16;

            // ---- load A1 fragments (swizzle-matched, conflict-free) ---------
            u32 ah[4][4], al[4][4];
            #pragma unroll
            for (int ks = 0; ks < 4; ks++)
                #pragma unroll
                for (int w = 0; w < 4; w++) {
                    int bank = lane ^ (ks * 4) ^ ((w & 2) * 8);
                    ah[ks][w] = awc[(ks * 8 + w) * 32 + bank];
                    al[ks][w] = awc[(ks * 8 + w + 4) * 32 + bank];
                }

            // ---- layer 1: 16 nt, 3 balanced chains, unroll 2 ----------------
            u32 a2h[8][4], a2l[8][4];            // A2 hi+lo fully in registers
            #pragma unroll 2
            for (int nt = 0; nt < 16; nt++) {
                float c0[4] = {0.f, 0.f, 0.f, 0.f};
                float c1[4] = {0.f, 0.f, 0.f, 0.f};
                float c2[4] = {0.f, 0.f, 0.f, 0.f};
                #pragma unroll
                for (int ks = 0; ks < 4; ks++) {
                    uint4 B = w1f[(nt * 4 + ks) * 32 + lane];  // smem LDS.128
                    mma16(c0, ah[ks], B.x, B.y);   // Ah*Bh
                    mma16(c1, al[ks], B.x, B.y);   // (Al*SC)*Bh
                    mma16(c2, ah[ks], B.z, B.w);   // Ah*(Bl*SC)
                }
                int n = nt * 8 + t * 2;
                float s0f = fmaf(c1[0] + c2[0], INV_SC, c0[0]);
                float s1f = fmaf(c1[1] + c2[1], INV_SC, c0[1]);
                float s2f = fmaf(c1[2] + c2[2], INV_SC, c0[2]);
                float s3f = fmaf(c1[3] + c2[3], INV_SC, c0[3]);
                float h0 = fmaxf(fmaf(s0f, INV_S1, sB1[n]),     0.f) * S2;
                float h1 = fmaxf(fmaf(s1f, INV_S1, sB1[n + 1]), 0.f) * S2;
                float h2 = fmaxf(fmaf(s2f, INV_S1, sB1[n]),     0.f) * S2;
                float h3 = fmaxf(fmaf(s3f, INV_S1, sB1[n + 1]), 0.f) * S2;
                int ks2 = nt >> 1, w0 = (nt & 1) * 2;
                u32 hA = pk2(h0, h1), hB = pk2(h2, h3);
                a2h[ks2][w0]     = hA;
                a2h[ks2][w0 + 1] = hB;
                float r0, r1, r2, r3;
                upk2(hA, r0, r1); upk2(hB, r2, r3);
                a2l[ks2][w0]     = pk2((h0 - r0) * SC, (h1 - r1) * SC);
                a2l[ks2][w0 + 1] = pk2((h2 - r2) * SC, (h3 - r3) * SC);
            }

            // ---- layer 2: 16 nt, 2 chains (w2 residual dropped), unroll 2 ---
            float plo = 0.f, phi = 0.f;
            #pragma unroll 2
            for (int nt = 0; nt < 16; nt++) {
                float c0[4] = {0.f, 0.f, 0.f, 0.f};
                float c1[4] = {0.f, 0.f, 0.f, 0.f};
                #pragma unroll
                for (int ks = 0; ks < 8; ks++) {
                    uint2 B = w2h[(nt * 8 + ks) * 32 + lane]; // smem LDS.64
                    mma16(c0, a2h[ks], B.x, B.y);
                    mma16(c1, a2l[ks], B.x, B.y);
                }
                int n = nt * 8 + t * 2;
                float w30 = sW3[n], w31 = sW3[n + 1];
                float bb0 = sB2[n], bb1 = sB2[n + 1];
                float v0 = fmaf(fmaf(c1[0], INV_SC, c0[0]), INV_S2, bb0);
                float v1 = fmaf(fmaf(c1[1], INV_SC, c0[1]), INV_S2, bb1);
                float v2 = fmaf(fmaf(c1[2], INV_SC, c0[2]), INV_S2, bb0);
                float v3 = fmaf(fmaf(c1[3], INV_SC, c0[3]), INV_S2, bb1);
                plo = fmaf(fmaxf(v0, 0.f), w30, plo);
                plo = fmaf(fmaxf(v1, 0.f), w31, plo);
                phi = fmaf(fmaxf(v2, 0.f), w30, phi);
                phi = fmaf(fmaxf(v3, 0.f), w31, phi);
            }
            plo += __shfl_xor_sync(0xffffffffu, plo, 1);
            plo += __shfl_xor_sync(0xffffffffu, plo, 2);
            phi += __shfl_xor_sync(0xffffffffu, phi, 1);
            phi += __shfl_xor_sync(0xffffffffu, phi, 2);
            if (t == 0) {
                out[pbase + g]     = plo + bb3;
                out[pbase + g + 8] = phi + bb3;
            }
            p ^= 1;
        }
    }
}

// ---------------- launch ------------------------------------------------------
extern "C" void kernel_launch(void* const* d_in, const int* in_sizes, int n_in,
                              void* d_out, int out_size) {
    const float* coords = (const float*)d_in[0];
    const float* pxy    = (const float*)d_in[1];
    const float* pyz    = (const float*)d_in[2];
    const float* pxz    = (const float*)d_in[3];
    const float* w1     = (const float*)d_in[4];
    const float* b1     = (const float*)d_in[5];
    const float* w2     = (const float*)d_in[6];
    const float* b2     = (const float*)d_in[7];
    const float* w3     = (const float*)d_in[8];
    const float* b3     = (const float*)d_in[9];
    float* out = (float*)d_out;

    int M = in_sizes[0] / 3;       // 1048576
    int nslices = M / 16;          // 65536

    prep_kernel<<<864, 256>>>(pxy, pyz, pxz, w1, w2);

    int dev = 0, nsm = 148;
    cudaGetDevice(&dev);
    cudaDeviceGetAttribute(&nsm, cudaDevAttrMultiProcessorCount, dev);

    cudaFuncSetAttribute(fused_kernel, cudaFuncAttributeMaxDynamicSharedMemorySize, SMEM_BYTES);
    fused_kernel<<<nsm, 512, SMEM_BYTES>>>(coords, b1, b2, w3, b3, out, nslices);
}